// round 14
// baseline (speedup 1.0000x reference)
#include <cuda_runtime.h>
#include <cuda_bf16.h>
#include <cstdint>

#define NB   8
#define NS   2048
#define NH   256
#define NHH  128
#define NP   64
#define NQG  20
#define NTOK (NB*NS)

// ---- scratch (device globals; no allocation allowed) ----
__device__ float g_e[NTOK];              // exp(sim logit), clamped
__device__ float g_conf[NTOK];           // sigmoid(conf logit)
__device__ float g_Z[NB*NQG];            // in-group sum of exp
__device__ float g_cnt[NB*NQG];          // group counts
__device__ float g_W[NB*NQG*NP];         // exp-weighted param sums
__device__ float g_T[NB*NQG*NP];         // plain param sums
__device__ float g_tall[NB*NP];          // per-batch total param sums
__device__ __nv_bfloat16 g_Bh[256*256];  // weights [n=256][k=256], bf16 hi
__device__ __nv_bfloat16 g_Bl[256*256];  // bf16 lo residual

__device__ __forceinline__ uint32_t smem_u32(const void* p) {
    uint32_t a;
    asm("{ .reg .u64 t; cvta.to.shared.u64 t, %1; cvt.u32.u64 %0, t; }" : "=r"(a) : "l"(p));
    return a;
}
#define CP_ASYNC16(smaddr, gptr) \
    asm volatile("cp.async.cg.shared.global [%0], [%1], 16;" :: "r"(smaddr), "l"(gptr))
#define CP_COMMIT() asm volatile("cp.async.commit_group;" ::: "memory")
#define CP_WAIT1()  asm volatile("cp.async.wait_group 1;" ::: "memory")
#define CP_WAIT0()  asm volatile("cp.async.wait_group 0;" ::: "memory")

// ================= K_prep: transpose+split weights to bf16 hi/lo; zero accumulators =================
__global__ void k_prep(const float* __restrict__ sw1, const float* __restrict__ cw1) {
    int id = blockIdx.x * 256 + threadIdx.x;     // 32768
    int n = id >> 8, k = id & 255;               // n in [0,128), k in [0,256)
    float vs = sw1[(size_t)k * NHH + n];
    float vc = cw1[(size_t)k * NHH + n];
    __nv_bfloat16 hs = __float2bfloat16_rn(vs);
    __nv_bfloat16 ls = __float2bfloat16_rn(vs - __bfloat162float(hs));
    __nv_bfloat16 hc = __float2bfloat16_rn(vc);
    __nv_bfloat16 lc = __float2bfloat16_rn(vc - __bfloat162float(hc));
    g_Bh[n * 256 + k] = hs;
    g_Bl[n * 256 + k] = ls;
    g_Bh[(128 + n) * 256 + k] = hc;
    g_Bl[(128 + n) * 256 + k] = lc;
    if (id < NB * NQG * NP) { g_W[id] = 0.f; g_T[id] = 0.f; }
    if (id < NB * NQG) { g_Z[id] = 0.f; g_cnt[id] = 0.f; }
    if (id < NB * NP) g_tall[id] = 0.f;
}

// ================= K_mlp: split-N (M=128, N=128/CTA), 2 CTAs/SM =================
#define MT 128
#define KC 64
#define NCHUNK (NH/KC)
#define KST 72
// halves layout in dynamic smem:
#define SM_AH 0
#define SM_AL (128*KST)                  /* 9216  */
#define SM_B0 (2*128*KST)                /* 18432 */
#define BBUF  (2*128*KST)                /* 18432 halves per buffer (hi+lo) */
#define BLOFF (128*KST)                  /* 9216  */
#define MLP_SMEM ((SM_B0 + 2*BBUF) * 2)  /* 110592 bytes */

__device__ __forceinline__ void mma_bf16(float d[4], uint32_t a0, uint32_t a1,
                                         uint32_t a2, uint32_t a3,
                                         uint32_t b0, uint32_t b1) {
    asm volatile(
        "mma.sync.aligned.m16n8k16.row.col.f32.bf16.bf16.f32 "
        "{%0,%1,%2,%3}, {%4,%5,%6,%7}, {%8,%9}, {%0,%1,%2,%3};"
        : "+f"(d[0]), "+f"(d[1]), "+f"(d[2]), "+f"(d[3])
        : "r"(a0), "r"(a1), "r"(a2), "r"(a3), "r"(b0), "r"(b1));
}

__global__ __launch_bounds__(256, 2)
void k_mlp(const float* __restrict__ x,
           const float* __restrict__ sb1, const float* __restrict__ sb2,
           const float* __restrict__ cb1, const float* __restrict__ cb2,
           const float* __restrict__ sw2, const float* __restrict__ cw2)
{
    extern __shared__ __nv_bfloat16 sm[];
    __shared__ float b1s[128], w2s[128];
    __shared__ float part[128][2];

    const int tid  = threadIdx.x;
    const int wid  = tid >> 5;
    const int lane = tid & 31;
    const int gid  = lane >> 2;
    const int tig  = lane & 3;
    const int mw   = wid & 3;
    const int nw   = wid >> 2;      // 0..1
    const int m0w  = mw * 32;
    const int n0w  = nw * 64;
    const int mblk = blockIdx.x >> 1;
    const int half = blockIdx.x & 1;       // 0 = sim, 1 = conf
    const int row0 = mblk * MT;
    const int nbase = half * 128;
    const uint32_t smb = smem_u32(sm);

    if (tid < 128) {
        b1s[tid] = half ? cb1[tid] : sb1[tid];
        w2s[tid] = half ? cw2[tid] : sw2[tid];
    }

    float d[2][8][4];
    #pragma unroll
    for (int mi = 0; mi < 2; ++mi)
        #pragma unroll
        for (int ni = 0; ni < 8; ++ni)
            #pragma unroll
            for (int j = 0; j < 4; ++j) d[mi][ni][j] = 0.f;

    // ---- issue B chunk 0 (cp.async): 128 n-rows x 64 k, hi+lo ----
    #pragma unroll
    for (int i = 0; i < 4; ++i) {
        int idx = tid * 4 + i;               // 0..1023
        int n = idx >> 3, k = (idx & 7) * 8;
        uint32_t dh = smb + 2 * (SM_B0 + n * KST + k);
        CP_ASYNC16(dh, &g_Bh[(nbase + n) * 256 + k]);
        CP_ASYNC16(dh + 2 * BLOFF, &g_Bl[(nbase + n) * 256 + k]);
    }
    CP_COMMIT();

    // ---- load A chunk 0 into regs (8 float4/thread) ----
    float4 av[8];
    #pragma unroll
    for (int i = 0; i < 8; ++i) {
        int idx = tid * 8 + i;               // 0..2047
        int row = idx >> 4, k = (idx & 15) * 4;
        av[i] = *(const float4*)&x[(size_t)(row0 + row) * NH + k];
    }

    for (int c = 0; c < NCHUNK; ++c) {
        const int buf = c & 1;
        if (c < NCHUNK - 1) {
            const int kb = (c + 1) * KC;
            #pragma unroll
            for (int i = 0; i < 4; ++i) {
                int idx = tid * 4 + i;
                int n = idx >> 3, k = (idx & 7) * 8;
                uint32_t dh = smb + 2 * (SM_B0 + (buf ^ 1) * BBUF + n * KST + k);
                CP_ASYNC16(dh, &g_Bh[(nbase + n) * 256 + kb + k]);
                CP_ASYNC16(dh + 2 * BLOFF, &g_Bl[(nbase + n) * 256 + kb + k]);
            }
            CP_COMMIT();
        }
        // convert + store A regs (chunk c)
        #pragma unroll
        for (int i = 0; i < 8; ++i) {
            int idx = tid * 8 + i;
            int row = idx >> 4, k = (idx & 15) * 4;
            float4 v = av[i];
            __nv_bfloat16 h0 = __float2bfloat16_rn(v.x), h1 = __float2bfloat16_rn(v.y);
            __nv_bfloat16 h2 = __float2bfloat16_rn(v.z), h3 = __float2bfloat16_rn(v.w);
            __nv_bfloat162 hA = {h0, h1}, hB = {h2, h3};
            __nv_bfloat162 lA = {__float2bfloat16_rn(v.x - __bfloat162float(h0)),
                                 __float2bfloat16_rn(v.y - __bfloat162float(h1))};
            __nv_bfloat162 lB = {__float2bfloat16_rn(v.z - __bfloat162float(h2)),
                                 __float2bfloat16_rn(v.w - __bfloat162float(h3))};
            uint2 hw = {*(uint32_t*)&hA, *(uint32_t*)&hB};
            uint2 lw = {*(uint32_t*)&lA, *(uint32_t*)&lB};
            *(uint2*)&sm[SM_AH + row * KST + k] = hw;
            *(uint2*)&sm[SM_AL + row * KST + k] = lw;
        }
        if (c < NCHUNK - 1) {
            const int kb = (c + 1) * KC;
            #pragma unroll
            for (int i = 0; i < 8; ++i) {
                int idx = tid * 8 + i;
                int row = idx >> 4, k = (idx & 15) * 4;
                av[i] = *(const float4*)&x[(size_t)(row0 + row) * NH + kb + k];
            }
        }
        if (c < NCHUNK - 1) { CP_WAIT1(); } else { CP_WAIT0(); }
        __syncthreads();

        const int B0 = SM_B0 + buf * BBUF;
        #pragma unroll
        for (int ks = 0; ks < KC / 16; ++ks) {
            const int kk = ks * 16;
            uint32_t ah[2][4], al[2][4];
            #pragma unroll
            for (int mi = 0; mi < 2; ++mi) {
                int off = (m0w + mi * 16 + gid) * KST + kk + 2 * tig;
                ah[mi][0] = *(const uint32_t*)&sm[SM_AH + off];
                ah[mi][1] = *(const uint32_t*)&sm[SM_AH + off + 8 * KST];
                ah[mi][2] = *(const uint32_t*)&sm[SM_AH + off + 8];
                ah[mi][3] = *(const uint32_t*)&sm[SM_AH + off + 8 * KST + 8];
                al[mi][0] = *(const uint32_t*)&sm[SM_AL + off];
                al[mi][1] = *(const uint32_t*)&sm[SM_AL + off + 8 * KST];
                al[mi][2] = *(const uint32_t*)&sm[SM_AL + off + 8];
                al[mi][3] = *(const uint32_t*)&sm[SM_AL + off + 8 * KST + 8];
            }
            #pragma unroll
            for (int ni = 0; ni < 8; ++ni) {
                int offb = B0 + (n0w + ni * 8 + gid) * KST + kk + 2 * tig;
                uint32_t b0 = *(const uint32_t*)&sm[offb];
                uint32_t b1 = *(const uint32_t*)&sm[offb + 8];
                #pragma unroll
                for (int mi = 0; mi < 2; ++mi) {
                    mma_bf16(d[mi][ni], ah[mi][0], ah[mi][1], ah[mi][2], ah[mi][3], b0, b1);
                    mma_bf16(d[mi][ni], al[mi][0], al[mi][1], al[mi][2], al[mi][3], b0, b1);
                }
            }
            #pragma unroll
            for (int ni = 0; ni < 8; ++ni) {
                int offb = B0 + BLOFF + (n0w + ni * 8 + gid) * KST + kk + 2 * tig;
                uint32_t b0 = *(const uint32_t*)&sm[offb];
                uint32_t b1 = *(const uint32_t*)&sm[offb + 8];
                #pragma unroll
                for (int mi = 0; mi < 2; ++mi)
                    mma_bf16(d[mi][ni], ah[mi][0], ah[mi][1], ah[mi][2], ah[mi][3], b0, b1);
            }
        }
        __syncthreads();
    }

    // ---- epilogue: bias + relu + w2-dot over this warp's 64 cols ----
    float p[2][2];
    #pragma unroll
    for (int mi = 0; mi < 2; ++mi) {
        p[mi][0] = 0.f; p[mi][1] = 0.f;
        #pragma unroll
        for (int ni = 0; ni < 8; ++ni) {
            int cb = n0w + ni * 8 + 2 * tig;
            #pragma unroll
            for (int j = 0; j < 2; ++j) {
                float h0 = fmaxf(d[mi][ni][j]     + b1s[cb + j], 0.f);
                float h1 = fmaxf(d[mi][ni][2 + j] + b1s[cb + j], 0.f);
                p[mi][0] = fmaf(h0, w2s[cb + j], p[mi][0]);
                p[mi][1] = fmaf(h1, w2s[cb + j], p[mi][1]);
            }
        }
    }
    #pragma unroll
    for (int off = 1; off <= 2; off <<= 1) {
        #pragma unroll
        for (int mi = 0; mi < 2; ++mi) {
            p[mi][0] += __shfl_xor_sync(0xffffffffu, p[mi][0], off);
            p[mi][1] += __shfl_xor_sync(0xffffffffu, p[mi][1], off);
        }
    }
    if (tig == 0) {
        #pragma unroll
        for (int mi = 0; mi < 2; ++mi) {
            part[m0w + mi * 16 + gid][nw]     = p[mi][0];
            part[m0w + mi * 16 + gid + 8][nw] = p[mi][1];
        }
    }
    __syncthreads();
    if (tid < 128) {
        int row = row0 + tid;
        if (half == 0) {
            float sv = part[tid][0] + part[tid][1] + sb2[0];
            g_e[row] = __expf(fminf(sv, 80.f));     // no-max softmax term (NaN guard)
        } else {
            float cl = part[tid][0] + part[tid][1] + cb2[0];
            g_conf[row] = 1.f / (1.f + __expf(-cl));
        }
    }
}

// ================= K_accum: Z/count + per-group weighted sums + tall (piggybacked) =================
__global__ __launch_bounds__(256) void k_accum(const float* __restrict__ px,
                                               const int* __restrict__ qs) {
    const int b = blockIdx.x >> 5;
    const int chunk = blockIdx.x & 31;
    const int t0 = b * NS + chunk * 64;
    const int p = threadIdx.x & 63;
    const int u = threadIdx.x >> 6;
    const int bg = b * NQG;
    __shared__ float accW[4][NQG][NP];
    __shared__ float accT[4][NQG][NP];
    __shared__ float tpart[4][NP];
    __shared__ float esh[64];
    __shared__ int   qsh[64];
    __shared__ float Zsh[NQG];
    __shared__ int   csh[NQG];
    if (threadIdx.x < NQG) { Zsh[threadIdx.x] = 0.f; csh[threadIdx.x] = 0; }
    #pragma unroll
    for (int g = 0; g < NQG; ++g) { accW[u][g][p] = 0.f; accT[u][g][p] = 0.f; }
    __syncthreads();
    if (threadIdx.x < 64) {
        int q = qs[t0 + threadIdx.x];
        qsh[threadIdx.x] = q;
        float e = g_e[t0 + threadIdx.x];
        esh[threadIdx.x] = e;
        atomicAdd(&Zsh[q], e);
        atomicAdd(&csh[q], 1);
    }
    __syncthreads();
    const int tb = u * 16;
    float pxv[16];
    const float* base = px + (size_t)(t0 + tb) * NP + p;
    #pragma unroll
    for (int k = 0; k < 16; ++k) pxv[k] = base[(size_t)k * NP];
    #pragma unroll
    for (int k = 0; k < 16; ++k) {
        int g = qsh[tb + k];
        accW[u][g][p] = fmaf(esh[tb + k], pxv[k], accW[u][g][p]);
        accT[u][g][p] += pxv[k];
    }
    __syncthreads();
    // flush W/T; thread tid owns (g = u + 4k, p) for k=0..4 — accumulate tall partial on the fly
    {
        float tsum = 0.f;
        #pragma unroll
        for (int k = 0; k < 5; ++k) {
            int g = u + 4 * k;
            float w = accW[0][g][p] + accW[1][g][p] + accW[2][g][p] + accW[3][g][p];
            float t = accT[0][g][p] + accT[1][g][p] + accT[2][g][p] + accT[3][g][p];
            tsum += t;
            atomicAdd(&g_W[(bg + g) * NP + p], w);
            atomicAdd(&g_T[(bg + g) * NP + p], t);
        }
        tpart[u][p] = tsum;
    }
    if (threadIdx.x < NQG) {
        atomicAdd(&g_Z[bg + threadIdx.x], Zsh[threadIdx.x]);
        atomicAdd(&g_cnt[bg + threadIdx.x], (float)csh[threadIdx.x]);
    }
    __syncthreads();
    if (threadIdx.x < 64)
        atomicAdd(&g_tall[b * NP + threadIdx.x],
                  tpart[0][threadIdx.x] + tpart[1][threadIdx.x] +
                  tpart[2][threadIdx.x] + tpart[3][threadIdx.x]);
}

// ================= K_out: table-free streaming blend =================
__global__ __launch_bounds__(256) void k_out(const float* __restrict__ px,
                                             const int* __restrict__ qs,
                                             float* __restrict__ out) {
    int fid = blockIdx.x * 256 + threadIdx.x;   // 262144 float4
    int t  = fid >> 4;
    int pq = (fid & 15) * 4;
    int b  = t >> 11;
    int q  = __ldg(&qs[t]);
    int bq = b * NQG + q;
    float c = g_conf[t];
    float Z = g_Z[bq] + ((float)NS - g_cnt[bq]);
    float invZ = __frcp_rn(Z);
    float4 pv = *(const float4*)&px[(size_t)t * NP + pq];
    float4 W4 = *(const float4*)&g_W[bq * NP + pq];
    float4 T4 = *(const float4*)&g_T[bq * NP + pq];
    float4 A4 = *(const float4*)&g_tall[b * NP + pq];
    float ic = 1.f - c;
    float4 o;
    o.x = fmaf(c, pv.x, ic * ((W4.x + A4.x - T4.x) * invZ));
    o.y = fmaf(c, pv.y, ic * ((W4.y + A4.y - T4.y) * invZ));
    o.z = fmaf(c, pv.z, ic * ((W4.z + A4.z - T4.z) * invZ));
    o.w = fmaf(c, pv.w, ic * ((W4.w + A4.w - T4.w) * invZ));
    *(float4*)&out[(size_t)t * NP + pq] = o;
}

extern "C" void kernel_launch(void* const* d_in, const int* in_sizes, int n_in,
                              void* d_out, int out_size) {
    const float* x   = (const float*)d_in[0];
    const float* px  = (const float*)d_in[1];
    const float* sw1 = (const float*)d_in[2];
    const float* sb1 = (const float*)d_in[3];
    const float* sw2 = (const float*)d_in[4];
    const float* sb2 = (const float*)d_in[5];
    const float* cw1 = (const float*)d_in[6];
    const float* cb1 = (const float*)d_in[7];
    const float* cw2 = (const float*)d_in[8];
    const float* cb2 = (const float*)d_in[9];
    const int*   qs  = (const int*)d_in[10];
    float* out = (float*)d_out;

    cudaFuncSetAttribute(k_mlp, cudaFuncAttributeMaxDynamicSharedMemorySize, MLP_SMEM);

    k_prep<<<128, 256>>>(sw1, cw1);
    k_mlp<<<(NTOK / MT) * 2, 256, MLP_SMEM>>>(x, sb1, sb2, cb1, cb2, sw2, cw2);
    k_accum<<<NB * 32, 256>>>(px, qs);
    k_out<<<NTOK * 16 / 256, 256>>>(px, qs, out);
}

// round 16
// speedup vs baseline: 1.2070x; 1.2070x over previous
#include <cuda_runtime.h>
#include <cuda_bf16.h>
#include <cstdint>

#define NB   8
#define NS   2048
#define NH   256
#define NHH  128
#define NP   64
#define NQG  20
#define NTOK (NB*NS)

// ---- scratch (device globals; no allocation allowed) ----
__device__ float g_e[NTOK];              // exp(sim logit), clamped
__device__ float g_conf[NTOK];           // sigmoid(conf logit)
__device__ float g_Z[NB*NQG];            // in-group sum of exp
__device__ float g_cnt[NB*NQG];          // group counts
__device__ float g_W[NB*NQG*NP];         // exp-weighted param sums
__device__ float g_T[NB*NQG*NP];         // plain param sums
__device__ float g_tall[NB*NP];          // per-batch total param sums
__device__ __nv_bfloat16 g_Bh[256*256];  // weights [n=256][k=256], bf16 hi
__device__ __nv_bfloat16 g_Bl[256*256];  // bf16 lo residual

__device__ __forceinline__ uint32_t smem_u32(const void* p) {
    uint32_t a;
    asm("{ .reg .u64 t; cvta.to.shared.u64 t, %1; cvt.u32.u64 %0, t; }" : "=r"(a) : "l"(p));
    return a;
}
#define CP_ASYNC16(smaddr, gptr) \
    asm volatile("cp.async.cg.shared.global [%0], [%1], 16;" :: "r"(smaddr), "l"(gptr))
#define CP_COMMIT() asm volatile("cp.async.commit_group;" ::: "memory")
#define CP_WAIT0()  asm volatile("cp.async.wait_group 0;" ::: "memory")

// ================= K_prep: transpose+split weights to bf16 hi/lo; zero accumulators =================
__global__ void k_prep(const float* __restrict__ sw1, const float* __restrict__ cw1) {
    int id = blockIdx.x * 256 + threadIdx.x;     // 32768
    int n = id >> 8, k = id & 255;               // n in [0,128), k in [0,256)
    float vs = sw1[(size_t)k * NHH + n];
    float vc = cw1[(size_t)k * NHH + n];
    __nv_bfloat16 hs = __float2bfloat16_rn(vs);
    __nv_bfloat16 ls = __float2bfloat16_rn(vs - __bfloat162float(hs));
    __nv_bfloat16 hc = __float2bfloat16_rn(vc);
    __nv_bfloat16 lc = __float2bfloat16_rn(vc - __bfloat162float(hc));
    g_Bh[n * 256 + k] = hs;
    g_Bl[n * 256 + k] = ls;
    g_Bh[(128 + n) * 256 + k] = hc;
    g_Bl[(128 + n) * 256 + k] = lc;
    if (id < NB * NQG * NP) { g_W[id] = 0.f; g_T[id] = 0.f; }
    if (id < NB * NQG) { g_Z[id] = 0.f; g_cnt[id] = 0.f; }
    if (id < NB * NP) g_tall[id] = 0.f;
}

// ================= K_mlp: fully double-buffered mma.sync bf16 split-GEMM =================
#define MT 128
#define KC 64
#define NCHUNK (NH/KC)
#define KST 72
// halves layout in dynamic smem:
//   abuf0 (AH|AL) : 0        .. 18432
//   abuf1 (AH|AL) : 18432    .. 36864
//   bbuf0 (BH|BL) : 36864    .. 73728
//   bbuf1 (BH|BL) : 73728    .. 110592
#define ABUF  (2*128*KST)                /* 18432 halves per A buffer */
#define ALOFF (128*KST)                  /* 9216  */
#define SM_B0 (2*ABUF)                   /* 36864 */
#define BBUF  (2*256*KST)                /* 36864 halves per B buffer */
#define BLOFF (256*KST)                  /* 18432 */
#define MLP_SMEM ((SM_B0 + 2*BBUF) * 2)  /* 221184 bytes */

__device__ __forceinline__ void mma_bf16(float d[4], uint32_t a0, uint32_t a1,
                                         uint32_t a2, uint32_t a3,
                                         uint32_t b0, uint32_t b1) {
    asm volatile(
        "mma.sync.aligned.m16n8k16.row.col.f32.bf16.bf16.f32 "
        "{%0,%1,%2,%3}, {%4,%5,%6,%7}, {%8,%9}, {%0,%1,%2,%3};"
        : "+f"(d[0]), "+f"(d[1]), "+f"(d[2]), "+f"(d[3])
        : "r"(a0), "r"(a1), "r"(a2), "r"(a3), "r"(b0), "r"(b1));
}

__device__ __forceinline__ void conv_store_A(__nv_bfloat16* sm, int abase,
                                             const float4* av, int tid) {
    #pragma unroll
    for (int i = 0; i < 4; ++i) {
        int idx = tid * 4 + i;
        int row = idx >> 4, k = (idx & 15) * 4;
        float4 v = av[i];
        __nv_bfloat16 h0 = __float2bfloat16_rn(v.x), h1 = __float2bfloat16_rn(v.y);
        __nv_bfloat16 h2 = __float2bfloat16_rn(v.z), h3 = __float2bfloat16_rn(v.w);
        __nv_bfloat162 hA = {h0, h1}, hB = {h2, h3};
        __nv_bfloat162 lA = {__float2bfloat16_rn(v.x - __bfloat162float(h0)),
                             __float2bfloat16_rn(v.y - __bfloat162float(h1))};
        __nv_bfloat162 lB = {__float2bfloat16_rn(v.z - __bfloat162float(h2)),
                             __float2bfloat16_rn(v.w - __bfloat162float(h3))};
        uint2 hw = {*(uint32_t*)&hA, *(uint32_t*)&hB};
        uint2 lw = {*(uint32_t*)&lA, *(uint32_t*)&lB};
        *(uint2*)&sm[abase + row * KST + k] = hw;
        *(uint2*)&sm[abase + ALOFF + row * KST + k] = lw;
    }
}

__global__ __launch_bounds__(512, 1)
void k_mlp(const float* __restrict__ x,
           const float* __restrict__ sb1, const float* __restrict__ sb2,
           const float* __restrict__ cb1, const float* __restrict__ cb2,
           const float* __restrict__ sw2, const float* __restrict__ cw2)
{
    extern __shared__ __nv_bfloat16 sm[];
    __shared__ float b1s[256], w2s[256];
    __shared__ float part[128][4];

    const int tid  = threadIdx.x;
    const int wid  = tid >> 5;
    const int lane = tid & 31;
    const int gid  = lane >> 2;
    const int tig  = lane & 3;
    const int mw   = wid & 3;
    const int nw   = wid >> 2;
    const int m0w  = mw * 32;
    const int n0w  = nw * 64;
    const int row0 = blockIdx.x * MT;
    const uint32_t smb = smem_u32(sm);

    if (tid < 256) {
        b1s[tid] = (tid < 128) ? sb1[tid] : cb1[tid - 128];
        w2s[tid] = (tid < 128) ? sw2[tid] : cw2[tid - 128];
    }

    float d[2][8][4];
    #pragma unroll
    for (int mi = 0; mi < 2; ++mi)
        #pragma unroll
        for (int ni = 0; ni < 8; ++ni)
            #pragma unroll
            for (int j = 0; j < 4; ++j) d[mi][ni][j] = 0.f;

    // ---- prologue: B0 in flight, A0 converted, A1 in regs ----
    #pragma unroll
    for (int i = 0; i < 4; ++i) {
        int idx = tid * 4 + i;
        int n = idx >> 3, k = (idx & 7) * 8;
        uint32_t dh = smb + 2 * (SM_B0 + n * KST + k);
        CP_ASYNC16(dh, &g_Bh[n * 256 + k]);
        CP_ASYNC16(dh + 2 * BLOFF, &g_Bl[n * 256 + k]);
    }
    CP_COMMIT();

    float4 av[4];
    #pragma unroll
    for (int i = 0; i < 4; ++i) {
        int idx = tid * 4 + i;
        int row = idx >> 4, k = (idx & 15) * 4;
        av[i] = *(const float4*)&x[(size_t)(row0 + row) * NH + k];
    }
    conv_store_A(sm, 0, av, tid);
    #pragma unroll
    for (int i = 0; i < 4; ++i) {
        int idx = tid * 4 + i;
        int row = idx >> 4, k = (idx & 15) * 4;
        av[i] = *(const float4*)&x[(size_t)(row0 + row) * NH + KC + k];
    }
    CP_WAIT0();
    __syncthreads();      // B0 + A0 ready

    for (int c = 0; c < NCHUNK; ++c) {
        const int buf = c & 1;
        const int nxt = buf ^ 1;
        // stage chunk c+1: B cp.async into bbuf[nxt], A regs -> abuf[nxt]
        if (c < NCHUNK - 1) {
            const int kb = (c + 1) * KC;
            #pragma unroll
            for (int i = 0; i < 4; ++i) {
                int idx = tid * 4 + i;
                int n = idx >> 3, k = (idx & 7) * 8;
                uint32_t dh = smb + 2 * (SM_B0 + nxt * BBUF + n * KST + k);
                CP_ASYNC16(dh, &g_Bh[n * 256 + kb + k]);
                CP_ASYNC16(dh + 2 * BLOFF, &g_Bl[n * 256 + kb + k]);
            }
            CP_COMMIT();
            conv_store_A(sm, nxt * ABUF, av, tid);   // hides under MMA below
        }
        if (c < NCHUNK - 2) {
            const int kb = (c + 2) * KC;
            #pragma unroll
            for (int i = 0; i < 4; ++i) {
                int idx = tid * 4 + i;
                int row = idx >> 4, k = (idx & 15) * 4;
                av[i] = *(const float4*)&x[(size_t)(row0 + row) * NH + kb + k];
            }
        }

        const int A0 = buf * ABUF;
        const int B0 = SM_B0 + buf * BBUF;
        #pragma unroll
        for (int ks = 0; ks < KC / 16; ++ks) {
            const int kk = ks * 16;
            uint32_t ah[2][4], al[2][4];
            #pragma unroll
            for (int mi = 0; mi < 2; ++mi) {
                int off = A0 + (m0w + mi * 16 + gid) * KST + kk + 2 * tig;
                ah[mi][0] = *(const uint32_t*)&sm[off];
                ah[mi][1] = *(const uint32_t*)&sm[off + 8 * KST];
                ah[mi][2] = *(const uint32_t*)&sm[off + 8];
                ah[mi][3] = *(const uint32_t*)&sm[off + 8 * KST + 8];
                al[mi][0] = *(const uint32_t*)&sm[off + ALOFF];
                al[mi][1] = *(const uint32_t*)&sm[off + ALOFF + 8 * KST];
                al[mi][2] = *(const uint32_t*)&sm[off + ALOFF + 8];
                al[mi][3] = *(const uint32_t*)&sm[off + ALOFF + 8 * KST + 8];
            }
            #pragma unroll
            for (int ni = 0; ni < 8; ++ni) {
                int offb = B0 + (n0w + ni * 8 + gid) * KST + kk + 2 * tig;
                uint32_t b0 = *(const uint32_t*)&sm[offb];
                uint32_t b1 = *(const uint32_t*)&sm[offb + 8];
                #pragma unroll
                for (int mi = 0; mi < 2; ++mi) {
                    mma_bf16(d[mi][ni], ah[mi][0], ah[mi][1], ah[mi][2], ah[mi][3], b0, b1);
                    mma_bf16(d[mi][ni], al[mi][0], al[mi][1], al[mi][2], al[mi][3], b0, b1);
                }
            }
            #pragma unroll
            for (int ni = 0; ni < 8; ++ni) {
                int offb = B0 + BLOFF + (n0w + ni * 8 + gid) * KST + kk + 2 * tig;
                uint32_t b0 = *(const uint32_t*)&sm[offb];
                uint32_t b1 = *(const uint32_t*)&sm[offb + 8];
                #pragma unroll
                for (int mi = 0; mi < 2; ++mi)
                    mma_bf16(d[mi][ni], ah[mi][0], ah[mi][1], ah[mi][2], ah[mi][3], b0, b1);
            }
        }
        if (c < NCHUNK - 1) CP_WAIT0();
        __syncthreads();    // next chunk's A stores + B arrival visible; bufs free
    }

    // ---- epilogue ----
    float p[2][2];
    #pragma unroll
    for (int mi = 0; mi < 2; ++mi) {
        p[mi][0] = 0.f; p[mi][1] = 0.f;
        #pragma unroll
        for (int ni = 0; ni < 8; ++ni) {
            int cb = n0w + ni * 8 + 2 * tig;
            #pragma unroll
            for (int j = 0; j < 2; ++j) {
                float h0 = fmaxf(d[mi][ni][j]     + b1s[cb + j], 0.f);
                float h1 = fmaxf(d[mi][ni][2 + j] + b1s[cb + j], 0.f);
                p[mi][0] = fmaf(h0, w2s[cb + j], p[mi][0]);
                p[mi][1] = fmaf(h1, w2s[cb + j], p[mi][1]);
            }
        }
    }
    #pragma unroll
    for (int off = 1; off <= 2; off <<= 1) {
        #pragma unroll
        for (int mi = 0; mi < 2; ++mi) {
            p[mi][0] += __shfl_xor_sync(0xffffffffu, p[mi][0], off);
            p[mi][1] += __shfl_xor_sync(0xffffffffu, p[mi][1], off);
        }
    }
    if (tig == 0) {
        #pragma unroll
        for (int mi = 0; mi < 2; ++mi) {
            part[m0w + mi * 16 + gid][nw]     = p[mi][0];
            part[m0w + mi * 16 + gid + 8][nw] = p[mi][1];
        }
    }
    __syncthreads();
    if (tid < 128) {
        int row = row0 + tid;
        float sv = part[tid][0] + part[tid][1] + sb2[0];
        float cl = part[tid][2] + part[tid][3] + cb2[0];
        g_e[row]    = __expf(fminf(sv, 80.f));      // no-max softmax term (NaN guard)
        g_conf[row] = 1.f / (1.f + __expf(-cl));
    }
}

// ================= K_accum: Z/count + per-group weighted sums + tall (piggybacked) =================
__global__ __launch_bounds__(256) void k_accum(const float* __restrict__ px,
                                               const int* __restrict__ qs) {
    const int b = blockIdx.x >> 5;
    const int chunk = blockIdx.x & 31;
    const int t0 = b * NS + chunk * 64;
    const int p = threadIdx.x & 63;
    const int u = threadIdx.x >> 6;
    const int bg = b * NQG;
    __shared__ float accW[4][NQG][NP];
    __shared__ float accT[4][NQG][NP];
    __shared__ float tpart[4][NP];
    __shared__ float esh[64];
    __shared__ int   qsh[64];
    __shared__ float Zsh[NQG];
    __shared__ int   csh[NQG];
    if (threadIdx.x < NQG) { Zsh[threadIdx.x] = 0.f; csh[threadIdx.x] = 0; }
    #pragma unroll
    for (int g = 0; g < NQG; ++g) { accW[u][g][p] = 0.f; accT[u][g][p] = 0.f; }
    __syncthreads();
    if (threadIdx.x < 64) {
        int q = qs[t0 + threadIdx.x];
        qsh[threadIdx.x] = q;
        float e = g_e[t0 + threadIdx.x];
        esh[threadIdx.x] = e;
        atomicAdd(&Zsh[q], e);
        atomicAdd(&csh[q], 1);
    }
    __syncthreads();
    const int tb = u * 16;
    float pxv[16];
    const float* base = px + (size_t)(t0 + tb) * NP + p;
    #pragma unroll
    for (int k = 0; k < 16; ++k) pxv[k] = base[(size_t)k * NP];
    #pragma unroll
    for (int k = 0; k < 16; ++k) {
        int g = qsh[tb + k];
        accW[u][g][p] = fmaf(esh[tb + k], pxv[k], accW[u][g][p]);
        accT[u][g][p] += pxv[k];
    }
    __syncthreads();
    {
        float tsum = 0.f;
        #pragma unroll
        for (int k = 0; k < 5; ++k) {
            int g = u + 4 * k;
            float w = accW[0][g][p] + accW[1][g][p] + accW[2][g][p] + accW[3][g][p];
            float t = accT[0][g][p] + accT[1][g][p] + accT[2][g][p] + accT[3][g][p];
            tsum += t;
            atomicAdd(&g_W[(bg + g) * NP + p], w);
            atomicAdd(&g_T[(bg + g) * NP + p], t);
        }
        tpart[u][p] = tsum;
    }
    if (threadIdx.x < NQG) {
        atomicAdd(&g_Z[bg + threadIdx.x], Zsh[threadIdx.x]);
        atomicAdd(&g_cnt[bg + threadIdx.x], (float)csh[threadIdx.x]);
    }
    __syncthreads();
    if (threadIdx.x < 64)
        atomicAdd(&g_tall[b * NP + threadIdx.x],
                  tpart[0][threadIdx.x] + tpart[1][threadIdx.x] +
                  tpart[2][threadIdx.x] + tpart[3][threadIdx.x]);
}

// ================= K_out: table-free streaming blend =================
__global__ __launch_bounds__(256) void k_out(const float* __restrict__ px,
                                             const int* __restrict__ qs,
                                             float* __restrict__ out) {
    int fid = blockIdx.x * 256 + threadIdx.x;   // 262144 float4
    int t  = fid >> 4;
    int pq = (fid & 15) * 4;
    int b  = t >> 11;
    int q  = __ldg(&qs[t]);
    int bq = b * NQG + q;
    float c = g_conf[t];
    float Z = g_Z[bq] + ((float)NS - g_cnt[bq]);
    float invZ = __frcp_rn(Z);
    float4 pv = *(const float4*)&px[(size_t)t * NP + pq];
    float4 W4 = *(const float4*)&g_W[bq * NP + pq];
    float4 T4 = *(const float4*)&g_T[bq * NP + pq];
    float4 A4 = *(const float4*)&g_tall[b * NP + pq];
    float ic = 1.f - c;
    float4 o;
    o.x = fmaf(c, pv.x, ic * ((W4.x + A4.x - T4.x) * invZ));
    o.y = fmaf(c, pv.y, ic * ((W4.y + A4.y - T4.y) * invZ));
    o.z = fmaf(c, pv.z, ic * ((W4.z + A4.z - T4.z) * invZ));
    o.w = fmaf(c, pv.w, ic * ((W4.w + A4.w - T4.w) * invZ));
    *(float4*)&out[(size_t)t * NP + pq] = o;
}

extern "C" void kernel_launch(void* const* d_in, const int* in_sizes, int n_in,
                              void* d_out, int out_size) {
    const float* x   = (const float*)d_in[0];
    const float* px  = (const float*)d_in[1];
    const float* sw1 = (const float*)d_in[2];
    const float* sb1 = (const float*)d_in[3];
    const float* sw2 = (const float*)d_in[4];
    const float* sb2 = (const float*)d_in[5];
    const float* cw1 = (const float*)d_in[6];
    const float* cb1 = (const float*)d_in[7];
    const float* cw2 = (const float*)d_in[8];
    const float* cb2 = (const float*)d_in[9];
    const int*   qs  = (const int*)d_in[10];
    float* out = (float*)d_out;

    cudaFuncSetAttribute(k_mlp, cudaFuncAttributeMaxDynamicSharedMemorySize, MLP_SMEM);

    k_prep<<<128, 256>>>(sw1, cw1);
    k_mlp<<<NTOK / MT, 512, MLP_SMEM>>>(x, sb1, sb2, cb1, cb2, sw2, cw2);
    k_accum<<<NB * 32, 256>>>(px, qs);
    k_out<<<NTOK * 16 / 256, 256>>>(px, qs, out);
}